// round 14
// baseline (speedup 1.0000x reference)
#include <cuda_runtime.h>
#include <cuda_fp16.h>
#include <cstdint>

#define MAXN 50000
#define MAXE 1600000
#define F_IN 512
#define C1 64      // heads*hid = 8*8
#define HEADS 8
#define CLS 16
#define SCAN_B 256

typedef unsigned long long ull;

// packed fp32x2 FMA (sm_103a)
#define FMA_F32X2(d, a, b, c) \
    asm("fma.rn.f32x2 %0, %1, %2, %3;" : "=l"(d) : "l"(a), "l"(b), "l"(c))
#define PACK_DUP_F32X2(d, f) \
    asm("mov.b64 %0, {%1, %1};" : "=l"(d) : "r"(__float_as_uint(f)))

// ---------------- scratch ----------------
__device__ __align__(16) int   g_deg[MAXN];        // zeroed via cudaMemsetAsync
__device__ __align__(16) int   g_tmp[MAXN];        // zeroed inside k_scan1
__device__ __align__(16) int   g_rowptr[MAXN + 1]; // block-local exclusive prefix
__device__ __align__(16) int   g_bsum[256];
__device__ __align__(16) int   g_boff[256];        // per-block offset
__device__            int      g_arrive = 0;       // last-block ticket (returns to 0 each call)
__device__ __align__(16) int   g_col[MAXE + MAXN + 8];
__device__ __align__(16) float g_h1[(size_t)MAXN * C1];
__device__ __align__(16) float g_asrc1[MAXN * HEADS];
__device__ __align__(16) float g_adst1[MAXN * HEADS];
__device__ __align__(16) float g_h1act[(size_t)MAXN * C1];
__device__ __align__(16) float g_h2[(size_t)MAXN * CLS];
__device__ __align__(16) float g_asrc2[MAXN];
__device__ __align__(16) float g_adst2[MAXN];

// global rowptr = block-local prefix + per-block offset
__device__ __forceinline__ int rowp(int i) {
    return g_rowptr[i] + g_boff[i >> 8];
}

// Per-block int64-vs-int32 probe: deterministic for fixed input.
__device__ __forceinline__ bool block_detect_is64(const int* w32, long long e0, int E) {
    int hi = 0;
    long long e = e0 + threadIdx.x;
    if (e < E) hi = w32[2 * e + 1];
    return !__syncthreads_or(hi != 0);
}

__device__ __forceinline__ int load_edge(const void* ei, bool is64, size_t pos) {
    return is64 ? (int)((const long long*)ei)[pos] : ((const int*)ei)[pos];
}

// ================= fused GEMM1 (f32x2 packed) + edge count =================
#define TK 32
__global__ __launch_bounds__(256) void k_gemm1_count(
    const float* __restrict__ x, const float* __restrict__ W,
    const float* __restrict__ attS, const float* __restrict__ attD,
    const void* __restrict__ ei, int n, int E, int GB)
{
    if (blockIdx.x >= GB) {
        long long e0 = (long long)(blockIdx.x - GB) * 256;
        bool is64 = block_detect_is64((const int*)ei, e0, E);
        long long e = e0 + threadIdx.x;
        if (e < E) {
            int d = load_edge(ei, is64, (size_t)E + e);
            if ((unsigned)d < (unsigned)n) atomicAdd(&g_deg[d], 1);
        }
        return;
    }

    __shared__ __align__(16) float xs[TK][256 + 4];
    __shared__ __align__(16) float ws[TK][64 + 4];
    int tid = threadIdx.x;
    int tx = tid & 7;       // col group (== head)
    int ty = tid >> 3;      // row group 0..31
    int r0 = blockIdx.x * 256;

    ull acc2[8][4];
#pragma unroll
    for (int r = 0; r < 8; r++)
#pragma unroll
        for (int c = 0; c < 4; c++) acc2[r][c] = 0ull;

    for (int kc = 0; kc < F_IN; kc += TK) {
#pragma unroll
        for (int i = 0; i < 8; i++) {
            int idx = tid + 256 * i;
            int row = idx >> 3;
            int k4  = idx & 7;
            float4 v = make_float4(0.f, 0.f, 0.f, 0.f);
            int gr = r0 + row;
            if (gr < n) v = *(const float4*)&x[(size_t)gr * F_IN + kc + k4 * 4];
            xs[k4 * 4 + 0][row] = v.x;
            xs[k4 * 4 + 1][row] = v.y;
            xs[k4 * 4 + 2][row] = v.z;
            xs[k4 * 4 + 3][row] = v.w;
        }
#pragma unroll
        for (int i = 0; i < 2; i++) {
            int idx = tid + 256 * i;
            int k  = idx >> 4;
            int c4 = idx & 15;
            float4 v = *(const float4*)&W[(size_t)(kc + k) * C1 + c4 * 4];
            ws[k][c4 * 4 + 0] = v.x;
            ws[k][c4 * 4 + 1] = v.y;
            ws[k][c4 * 4 + 2] = v.z;
            ws[k][c4 * 4 + 3] = v.w;
        }
        __syncthreads();
#pragma unroll
        for (int k = 0; k < TK; k++) {
            float4 xa = *(const float4*)&xs[k][ty * 8];
            float4 xb = *(const float4*)&xs[k][ty * 8 + 4];
            ull wv2[4];
            {
                const ulonglong2* wp = (const ulonglong2*)&ws[k][tx * 8];
                ulonglong2 w01 = wp[0];
                ulonglong2 w23 = wp[1];
                wv2[0] = w01.x; wv2[1] = w01.y;
                wv2[2] = w23.x; wv2[3] = w23.y;
            }
            ull xp[8];
            PACK_DUP_F32X2(xp[0], xa.x); PACK_DUP_F32X2(xp[1], xa.y);
            PACK_DUP_F32X2(xp[2], xa.z); PACK_DUP_F32X2(xp[3], xa.w);
            PACK_DUP_F32X2(xp[4], xb.x); PACK_DUP_F32X2(xp[5], xb.y);
            PACK_DUP_F32X2(xp[6], xb.z); PACK_DUP_F32X2(xp[7], xb.w);
#pragma unroll
            for (int r = 0; r < 8; r++)
#pragma unroll
                for (int c = 0; c < 4; c++)
                    FMA_F32X2(acc2[r][c], xp[r], wv2[c], acc2[r][c]);
        }
        __syncthreads();
    }

    float as[8], ad[8];
#pragma unroll
    for (int c = 0; c < 8; c++) { as[c] = attS[tx * 8 + c]; ad[c] = attD[tx * 8 + c]; }
#pragma unroll
    for (int r = 0; r < 8; r++) {
        int gr = r0 + ty * 8 + r;
        if (gr < n) {
            float a[8];
#pragma unroll
            for (int c = 0; c < 4; c++) {
                uint2 u = *(uint2*)&acc2[r][c];
                a[2 * c]     = __uint_as_float(u.x);
                a[2 * c + 1] = __uint_as_float(u.y);
            }
            float s = 0.f, d = 0.f;
#pragma unroll
            for (int c = 0; c < 8; c++) {
                s = fmaf(a[c], as[c], s);
                d = fmaf(a[c], ad[c], d);
            }
            float4 v0 = make_float4(a[0], a[1], a[2], a[3]);
            float4 v1 = make_float4(a[4], a[5], a[6], a[7]);
            *(float4*)&g_h1[(size_t)gr * C1 + tx * 8]     = v0;
            *(float4*)&g_h1[(size_t)gr * C1 + tx * 8 + 4] = v1;
            g_asrc1[gr * HEADS + tx] = s;
            g_adst1[gr * HEADS + tx] = d;
        }
    }
}

// ================= single-pass block scan (last block folds scan2) =================
__device__ __forceinline__ int warp_incl_scan(int x) {
#pragma unroll
    for (int o = 1; o < 32; o <<= 1) {
        int t = __shfl_up_sync(0xffffffffu, x, o);
        if ((threadIdx.x & 31) >= o) x += t;
    }
    return x;
}

__global__ void k_scan1(int n, int nb) {
    __shared__ int wsum[8];
    __shared__ int is_last;
    int i = blockIdx.x * SCAN_B + threadIdx.x;
    int lane = threadIdx.x & 31, wid = threadIdx.x >> 5;
    if (i < n) g_tmp[i] = 0;
    int v = (i < n) ? g_deg[i] + 1 : 0;     // +1 = self-loop
    int x = warp_incl_scan(v);
    if (lane == 31) wsum[wid] = x;
    __syncthreads();
    if (wid == 0) {
        int y = (lane < 8) ? wsum[lane] : 0;
#pragma unroll
        for (int o = 1; o < 8; o <<= 1) {
            int t = __shfl_up_sync(0xffffffffu, y, o);
            if (lane >= o) y += t;
        }
        if (lane < 8) wsum[lane] = y;
    }
    __syncthreads();
    int excl = x - v + (wid > 0 ? wsum[wid - 1] : 0);
    if (i <= n) g_rowptr[i] = excl;
    if (threadIdx.x == 0) g_bsum[blockIdx.x] = wsum[7];

    __threadfence();
    if (threadIdx.x == 0) {
        int t = atomicAdd(&g_arrive, 1);
        is_last = (t == gridDim.x - 1);
    }
    __syncthreads();
    if (is_last) {
        int tt = threadIdx.x;
        int vv = (tt < nb) ? g_bsum[tt] : 0;
        int xx = warp_incl_scan(vv);
        if (lane == 31) wsum[wid] = xx;
        __syncthreads();
        if (wid == 0) {
            int y = (lane < 8) ? wsum[lane] : 0;
#pragma unroll
            for (int o = 1; o < 8; o <<= 1) {
                int t2 = __shfl_up_sync(0xffffffffu, y, o);
                if (lane >= o) y += t2;
            }
            if (lane < 8) wsum[lane] = y;
        }
        __syncthreads();
        int ex2 = xx - vv + (wid > 0 ? wsum[wid - 1] : 0);
        if (tt < nb) g_boff[tt] = ex2;
        if (tt == 0) g_arrive = 0;
    }
}

// ================= scatter (edges then self-loops) =================
__global__ void k_scatter(const void* __restrict__ ei, int E, int n) {
    long long e0 = (long long)blockIdx.x * 256;
    bool is64 = block_detect_is64((const int*)ei, e0, E);
    long long i = e0 + threadIdx.x;
    int s, d;
    if (i < E) {
        d = load_edge(ei, is64, (size_t)E + i);
        if ((unsigned)d >= (unsigned)n) return;
        s = load_edge(ei, is64, (size_t)i);
        if ((unsigned)s >= (unsigned)n) s = 0;
    } else if (i < E + n) {
        s = d = (int)(i - E);
    } else return;
    int pos = rowp(d) + atomicAdd(&g_tmp[d], 1);
    g_col[pos] = s;
}

// ================= layer-1 edge softmax + aggregate + bias + elu =================
// 2 dst nodes per warp. Per half (hl = lane&15):
//   feature lanes: hl owns channels 4hl..4hl+3 (head hown = hl>>1)
//   exp lanes: (j = hl>>3, h = hl&7): lane exponentiates edges j and j+2 of each 4-group
// 4 edges per half per iteration; validity-masked, no prologue/tail.
__global__ __launch_bounds__(256) void agg1(const float* __restrict__ bias1, int n) {
    int gwarp = (blockIdx.x * blockDim.x + threadIdx.x) >> 5;
    int lane  = threadIdx.x & 31;
    int half  = lane >> 4;
    int hl    = lane & 15;
    int half0 = half << 4;
    int nd = gwarp * 2 + half;
    bool okn = nd < n;
    int ndc = okn ? nd : 0;
    int h    = hl & 7;
    int j    = hl >> 3;       // 0/1: edges j and j+2
    int hown = hl >> 1;

    float adv = g_adst1[ndc * HEADS + h];
    int beg = rowp(ndc);
    int end = okn ? rowp(ndc + 1) : beg;

    ull acc01 = 0ull, acc23 = 0ull;
    float den = 0.f;

    int iters = (end - beg + 3) >> 2;
    int oth = __shfl_xor_sync(0xffffffffu, iters, 16);
    int mx = iters > oth ? iters : oth;

    for (int k = 0; k < mx; k++) {
        int e0 = beg + 4 * k;
        bool v0 = e0 < end, v1 = e0 + 1 < end, v2 = e0 + 2 < end, v3 = e0 + 3 < end;
        int s0 = g_col[v0 ? e0     : beg];
        int s1 = g_col[v1 ? e0 + 1 : beg];
        int s2 = g_col[v2 ? e0 + 2 : beg];
        int s3 = g_col[v3 ? e0 + 3 : beg];
        // exp lanes: edge a = e0+j, edge b = e0+j+2
        int sa = j ? s1 : s0;
        int sb = j ? s3 : s2;
        float aa = g_asrc1[sa * HEADS + h] + adv;
        float ab = g_asrc1[sb * HEADS + h] + adv;
        ulonglong2 u0 = *(const ulonglong2*)&g_h1[(size_t)s0 * C1 + 4 * hl];
        ulonglong2 u1 = *(const ulonglong2*)&g_h1[(size_t)s1 * C1 + 4 * hl];
        ulonglong2 u2 = *(const ulonglong2*)&g_h1[(size_t)s2 * C1 + 4 * hl];
        ulonglong2 u3 = *(const ulonglong2*)&g_h1[(size_t)s3 * C1 + 4 * hl];
        aa = aa > 0.f ? aa : 0.2f * aa;
        ab = ab > 0.f ? ab : 0.2f * ab;
        float wa = __expf(aa);
        float wb = __expf(ab);
        wa = (j ? v1 : v0) ? wa : 0.f;
        wb = (j ? v3 : v2) ? wb : 0.f;
        den += wa + wb;
        float w0o = __shfl_sync(0xffffffffu, wa, half0 + hown);
        float w1o = __shfl_sync(0xffffffffu, wa, half0 + 8 + hown);
        float w2o = __shfl_sync(0xffffffffu, wb, half0 + hown);
        float w3o = __shfl_sync(0xffffffffu, wb, half0 + 8 + hown);
        ull wp0, wp1, wp2, wp3;
        PACK_DUP_F32X2(wp0, w0o);
        PACK_DUP_F32X2(wp1, w1o);
        PACK_DUP_F32X2(wp2, w2o);
        PACK_DUP_F32X2(wp3, w3o);
        FMA_F32X2(acc01, wp0, u0.x, acc01);
        FMA_F32X2(acc23, wp0, u0.y, acc23);
        FMA_F32X2(acc01, wp1, u1.x, acc01);
        FMA_F32X2(acc23, wp1, u1.y, acc23);
        FMA_F32X2(acc01, wp2, u2.x, acc01);
        FMA_F32X2(acc23, wp2, u2.y, acc23);
        FMA_F32X2(acc01, wp3, u3.x, acc01);
        FMA_F32X2(acc23, wp3, u3.y, acc23);
    }

    // fold den over j groups (lanes hl and hl^8 share head h)
    den += __shfl_xor_sync(0xffffffffu, den, 8);
    float deno = __shfl_sync(0xffffffffu, den, half0 + hown);

    if (okn) {
        uint2 ua = *(uint2*)&acc01;
        uint2 ub = *(uint2*)&acc23;
        float4 bv = *(const float4*)&bias1[4 * hl];
        float o0 = __uint_as_float(ua.x) / deno + bv.x;
        float o1 = __uint_as_float(ua.y) / deno + bv.y;
        float o2 = __uint_as_float(ub.x) / deno + bv.z;
        float o3 = __uint_as_float(ub.y) / deno + bv.w;
        o0 = o0 > 0.f ? o0 : expm1f(o0);
        o1 = o1 > 0.f ? o1 : expm1f(o1);
        o2 = o2 > 0.f ? o2 : expm1f(o2);
        o3 = o3 > 0.f ? o3 : expm1f(o3);
        *(float4*)&g_h1act[(size_t)nd * C1 + 4 * hl] = make_float4(o0, o1, o2, o3);
    }
}

// ================= GEMM2: h2 = h1act @ W2, fused scalar logits =================
__global__ __launch_bounds__(256) void gemm2(
    const float* __restrict__ W2, const float* __restrict__ aS,
    const float* __restrict__ aD, int n)
{
    __shared__ float ws[64 * 16];
    int tid = threadIdx.x;
    for (int i = tid; i < 64 * 16; i += 256) ws[i] = W2[i];
    __syncthreads();

    int warp = tid >> 5, lane = tid & 31;
    int row0 = (blockIdx.x * 8 + warp) * 2 + (lane >> 4);
    int c = lane & 15;
    bool ok = row0 < n;
    int row = ok ? row0 : 0;

    float xr[4];
#pragma unroll
    for (int j = 0; j < 4; j++) xr[j] = g_h1act[(size_t)row * C1 + c + 16 * j];

    float acc = 0.f;
#pragma unroll
    for (int k = 0; k < 64; k++) {
        float xk = __shfl_sync(0xffffffffu, xr[k >> 4], (lane & 16) | (k & 15));
        acc = fmaf(xk, ws[k * 16 + c], acc);
    }

    float ts = acc * aS[c];
    float td = acc * aD[c];
#pragma unroll
    for (int off = 8; off >= 1; off >>= 1) {
        ts += __shfl_xor_sync(0xffffffffu, ts, off);
        td += __shfl_xor_sync(0xffffffffu, td, off);
    }
    if (ok) {
        g_h2[(size_t)row * CLS + c] = acc;
        if (c == 0) { g_asrc2[row] = ts; g_adst2[row] = td; }
    }
}

// ================= layer-2 aggregate + bias + log_softmax =================
// 2 nodes per warp. Per half: lane owns channel c = hl; exp lane slot j = hl>>2
// (4 slots of 4 lanes) -> 1 exp + 1 asrc per 4 edges; den fold xor 4, 8.
__global__ __launch_bounds__(256) void agg2(
    const float* __restrict__ bias2, float* __restrict__ out, int n)
{
    int gwarp = (blockIdx.x * blockDim.x + threadIdx.x) >> 5;
    int lane = threadIdx.x & 31;
    int half = lane >> 4;
    int hl   = lane & 15;
    int half0 = half << 4;
    int node = gwarp * 2 + half;
    int c = hl;
    bool ok = node < n;
    int nd = ok ? node : 0;
    int j = hl >> 2;          // edge slot 0..3

    float adv = g_adst2[nd];
    int beg = rowp(nd);
    int end = ok ? rowp(nd + 1) : beg;

    float acc = 0.f, den = 0.f;
    int iters = (end - beg + 3) >> 2;
    int oth = __shfl_xor_sync(0xffffffffu, iters, 16);
    int mx = iters > oth ? iters : oth;

    for (int k = 0; k < mx; k++) {
        int e0 = beg + 4 * k;
        bool v0 = e0 < end, v1 = e0 + 1 < end, v2 = e0 + 2 < end, v3 = e0 + 3 < end;
        int s0 = g_col[v0 ? e0     : beg];
        int s1 = g_col[v1 ? e0 + 1 : beg];
        int s2 = g_col[v2 ? e0 + 2 : beg];
        int s3 = g_col[v3 ? e0 + 3 : beg];
        int sj = (j == 0) ? s0 : (j == 1) ? s1 : (j == 2) ? s2 : s3;
        bool vj = (j == 0) ? v0 : (j == 1) ? v1 : (j == 2) ? v2 : v3;
        float a = g_asrc2[sj] + adv;
        float f0 = g_h2[(size_t)s0 * CLS + c];
        float f1 = g_h2[(size_t)s1 * CLS + c];
        float f2 = g_h2[(size_t)s2 * CLS + c];
        float f3 = g_h2[(size_t)s3 * CLS + c];
        a = a > 0.f ? a : 0.2f * a;
        float w = __expf(a);
        w = vj ? w : 0.f;
        den += w;                                 // lane's slot; folded below
        float w0 = __shfl_sync(0xffffffffu, w, half0 + 0);
        float w1 = __shfl_sync(0xffffffffu, w, half0 + 4);
        float w2 = __shfl_sync(0xffffffffu, w, half0 + 8);
        float w3 = __shfl_sync(0xffffffffu, w, half0 + 12);
        acc = fmaf(w0, f0, acc);
        acc = fmaf(w1, f1, acc);
        acc = fmaf(w2, f2, acc);
        acc = fmaf(w3, f3, acc);
    }
    // den: lanes in group-of-4 hold identical slot sums; fold distinct slots
    den += __shfl_xor_sync(0xffffffffu, den, 4);
    den += __shfl_xor_sync(0xffffffffu, den, 8);

    float val = ok ? (acc / den + bias2[c]) : 0.f;
    float m = val;
#pragma unroll
    for (int off = 8; off >= 1; off >>= 1)
        m = fmaxf(m, __shfl_xor_sync(0xffffffffu, m, off));
    float ex = __expf(val - m);
    float s = ex;
#pragma unroll
    for (int off = 8; off >= 1; off >>= 1)
        s += __shfl_xor_sync(0xffffffffu, s, off);
    if (ok) out[(size_t)node * CLS + c] = val - m - __logf(s);
}

// ---------------- launch ----------------
extern "C" void kernel_launch(void* const* d_in, const int* in_sizes, int n_in,
                              void* d_out, int out_size) {
    const float* x     = (const float*)d_in[0];
    const void*  ei    = d_in[1];
    const float* W1    = (const float*)d_in[2];
    const float* attS1 = (const float*)d_in[3];
    const float* attD1 = (const float*)d_in[4];
    const float* bias1 = (const float*)d_in[5];
    const float* W2    = (const float*)d_in[6];
    const float* attS2 = (const float*)d_in[7];
    const float* attD2 = (const float*)d_in[8];
    const float* bias2 = (const float*)d_in[9];
    float* out = (float*)d_out;

    int n = in_sizes[0] / F_IN;      // 50000
    int E = in_sizes[1] / 2;         // 1600000

    void* p_deg = nullptr;
    cudaGetSymbolAddress(&p_deg, g_deg);
    cudaMemsetAsync(p_deg, 0, (size_t)n * sizeof(int));

    int GB = (n + 255) / 256;                 // gemm1 blocks (196)
    int CB = (E + 255) / 256;                 // count blocks (6250)
    int nb = (n + SCAN_B - 1) / SCAN_B;       // scan blocks (196)
    int AW = (n + 1) / 2;                     // 2-node warps

    k_gemm1_count<<<GB + CB, 256>>>(x, W1, attS1, attD1, ei, n, E, GB);
    k_scan1<<<nb, SCAN_B>>>(n, nb);
    k_scatter<<<(E + n + 255) / 256, 256>>>(ei, E, n);
    agg1 <<<(AW + 7) / 8, 256>>>(bias1, n);     // <- ncu lands here
    gemm2<<<(n + 15) / 16, 256>>>(W2, attS2, attD2, n);
    agg2 <<<(AW + 7) / 8, 256>>>(bias2, out, n);
}

// round 15
// speedup vs baseline: 1.2955x; 1.2955x over previous
#include <cuda_runtime.h>
#include <cuda_fp16.h>
#include <cstdint>

#define MAXN 50000
#define MAXE 1600000
#define F_IN 512
#define C1 64      // heads*hid = 8*8
#define HEADS 8
#define CLS 16
#define SCAN_B 256

typedef unsigned long long ull;

// packed fp32x2 FMA (sm_103a)
#define FMA_F32X2(d, a, b, c) \
    asm("fma.rn.f32x2 %0, %1, %2, %3;" : "=l"(d) : "l"(a), "l"(b), "l"(c))
#define PACK_DUP_F32X2(d, f) \
    asm("mov.b64 %0, {%1, %1};" : "=l"(d) : "r"(__float_as_uint(f)))

#define MMA16816(d0,d1,d2,d3,a0,a1,a2,a3,b0,b1) \
    asm volatile("mma.sync.aligned.m16n8k16.row.col.f32.f16.f16.f32 " \
        "{%0,%1,%2,%3}, {%4,%5,%6,%7}, {%8,%9}, {%0,%1,%2,%3};" \
        : "+f"(d0), "+f"(d1), "+f"(d2), "+f"(d3) \
        : "r"(a0), "r"(a1), "r"(a2), "r"(a3), "r"(b0), "r"(b1))

// ---------------- scratch ----------------
__device__ __align__(16) int   g_deg[MAXN];        // zeroed via cudaMemsetAsync
__device__ __align__(16) int   g_tmp[MAXN];        // zeroed inside k_scan1
__device__ __align__(16) int   g_rowptr[MAXN + 1]; // block-local exclusive prefix
__device__ __align__(16) int   g_bsum[256];
__device__ __align__(16) int   g_boff[256];        // per-block offset
__device__            int      g_arrive = 0;       // last-block ticket (returns to 0)
__device__ __align__(16) int   g_col[MAXE + MAXN + 8];
__device__ __align__(16) float g_h1[(size_t)MAXN * C1];
__device__ __align__(16) float g_asrc1[MAXN * HEADS];
__device__ __align__(16) float g_adst1[MAXN * HEADS];
__device__ __align__(16) float g_h1act[(size_t)MAXN * C1];
__device__ __align__(16) float g_h2[(size_t)MAXN * CLS];
__device__ __align__(16) float g_asrc2[MAXN];
__device__ __align__(16) float g_adst2[MAXN];

__device__ __forceinline__ int rowp(int i) {
    return g_rowptr[i] + g_boff[i >> 8];
}

__device__ __forceinline__ bool block_detect_is64(const int* w32, long long e0, int E) {
    int hi = 0;
    long long e = e0 + threadIdx.x;
    if (e < E) hi = w32[2 * e + 1];
    return !__syncthreads_or(hi != 0);
}

__device__ __forceinline__ int load_edge(const void* ei, bool is64, size_t pos) {
    return is64 ? (int)((const long long*)ei)[pos] : ((const int*)ei)[pos];
}

// ================= fused GEMM1 (fp16 HMMA) + edge count =================
// blocks [0, GB): gemm1 tiles of 128 rows x 64 cols; blocks [GB,...): degree count
#define XSS 36   // xs row stride (halfs)
#define WSS 36   // wsT row stride (halfs)
__global__ __launch_bounds__(256) void k_gemm1_count(
    const float* __restrict__ x, const float* __restrict__ W,
    const float* __restrict__ attS, const float* __restrict__ attD,
    const void* __restrict__ ei, int n, int E, int GB)
{
    if (blockIdx.x >= GB) {
        long long e0 = (long long)(blockIdx.x - GB) * 256;
        bool is64 = block_detect_is64((const int*)ei, e0, E);
        long long e = e0 + threadIdx.x;
        if (e < E) {
            int d = load_edge(ei, is64, (size_t)E + e);
            if ((unsigned)d < (unsigned)n) atomicAdd(&g_deg[d], 1);
        }
        return;
    }

    __shared__ __align__(16) __half xs[128 * XSS];   // [row][k] halfs
    __shared__ __align__(16) __half wsT[64 * WSS];   // [n][k]   halfs (transposed W)
    int tid = threadIdx.x;
    int w = tid >> 5, lane = tid & 31;
    int r0 = blockIdx.x * 128;
    int lq = lane >> 2;        // 0..7
    int lr = lane & 3;         // 0..3

    float acc[8][4];
#pragma unroll
    for (int t = 0; t < 8; t++)
#pragma unroll
        for (int q = 0; q < 4; q++) acc[t][q] = 0.f;

    for (int kc = 0; kc < F_IN; kc += 32) {
        // x tile 128x32 fp32 -> fp16 smem
#pragma unroll
        for (int i = 0; i < 4; i++) {
            int idx = tid + 256 * i;       // 1024 float4
            int row = idx >> 3;
            int q   = idx & 7;
            float4 v = make_float4(0.f, 0.f, 0.f, 0.f);
            int gr = r0 + row;
            if (gr < n) v = *(const float4*)&x[(size_t)gr * F_IN + kc + q * 4];
            __half2 h01 = __floats2half2_rn(v.x, v.y);
            __half2 h23 = __floats2half2_rn(v.z, v.w);
            uint2 pv;
            pv.x = *(unsigned*)&h01; pv.y = *(unsigned*)&h23;
            *(uint2*)&xs[row * XSS + q * 4] = pv;    // 72*row+8q bytes: 8B aligned
        }
        // W tile 32x64 fp32 -> transposed fp16 smem wsT[n][k]
#pragma unroll
        for (int i = 0; i < 2; i++) {
            int idx = tid + 256 * i;       // 512 float4
            int k  = idx >> 4;
            int c4 = (idx & 15) * 4;
            float4 v = *(const float4*)&W[(size_t)(kc + k) * C1 + c4];
            wsT[(c4 + 0) * WSS + k] = __float2half_rn(v.x);
            wsT[(c4 + 1) * WSS + k] = __float2half_rn(v.y);
            wsT[(c4 + 2) * WSS + k] = __float2half_rn(v.z);
            wsT[(c4 + 3) * WSS + k] = __float2half_rn(v.w);
        }
        __syncthreads();
#pragma unroll
        for (int s = 0; s < 2; s++) {      // two k16 steps
            int r  = w * 16 + lq;
            int kb = s * 16 + lr * 2;
            unsigned a0 = *(const unsigned*)&xs[r * XSS + kb];
            unsigned a1 = *(const unsigned*)&xs[(r + 8) * XSS + kb];
            unsigned a2 = *(const unsigned*)&xs[r * XSS + kb + 8];
            unsigned a3 = *(const unsigned*)&xs[(r + 8) * XSS + kb + 8];
#pragma unroll
            for (int t = 0; t < 8; t++) {
                int nn = t * 8 + lq;
                unsigned b0 = *(const unsigned*)&wsT[nn * WSS + kb];
                unsigned b1 = *(const unsigned*)&wsT[nn * WSS + kb + 8];
                MMA16816(acc[t][0], acc[t][1], acc[t][2], acc[t][3],
                         a0, a1, a2, a3, b0, b1);
            }
        }
        __syncthreads();
    }

    // epilogue: lane holds rows (gra, grb), cols 8t+c0, 8t+c0+1 per tile t (t == head)
    int c0 = 2 * lr;
    int gra = r0 + w * 16 + lq;
    int grb = gra + 8;
    bool oka = gra < n, okb = grb < n;
#pragma unroll
    for (int t = 0; t < 8; t++) {
        float e0 = __ldg(&attS[8 * t + c0]);
        float e1 = __ldg(&attS[8 * t + c0 + 1]);
        float f0 = __ldg(&attD[8 * t + c0]);
        float f1 = __ldg(&attD[8 * t + c0 + 1]);
        float sa = fmaf(acc[t][0], e0, acc[t][1] * e1);
        float da = fmaf(acc[t][0], f0, acc[t][1] * f1);
        float sb = fmaf(acc[t][2], e0, acc[t][3] * e1);
        float db = fmaf(acc[t][2], f0, acc[t][3] * f1);
        sa += __shfl_xor_sync(0xffffffffu, sa, 1);
        sa += __shfl_xor_sync(0xffffffffu, sa, 2);
        da += __shfl_xor_sync(0xffffffffu, da, 1);
        da += __shfl_xor_sync(0xffffffffu, da, 2);
        sb += __shfl_xor_sync(0xffffffffu, sb, 1);
        sb += __shfl_xor_sync(0xffffffffu, sb, 2);
        db += __shfl_xor_sync(0xffffffffu, db, 1);
        db += __shfl_xor_sync(0xffffffffu, db, 2);
        if (oka) {
            *(float2*)&g_h1[(size_t)gra * C1 + 8 * t + c0] = make_float2(acc[t][0], acc[t][1]);
            if (lr == 0) { g_asrc1[gra * HEADS + t] = sa; g_adst1[gra * HEADS + t] = da; }
        }
        if (okb) {
            *(float2*)&g_h1[(size_t)grb * C1 + 8 * t + c0] = make_float2(acc[t][2], acc[t][3]);
            if (lr == 0) { g_asrc1[grb * HEADS + t] = sb; g_adst1[grb * HEADS + t] = db; }
        }
    }
}

// ================= single-pass block scan (last block folds scan2) =================
__device__ __forceinline__ int warp_incl_scan(int x) {
#pragma unroll
    for (int o = 1; o < 32; o <<= 1) {
        int t = __shfl_up_sync(0xffffffffu, x, o);
        if ((threadIdx.x & 31) >= o) x += t;
    }
    return x;
}

__global__ void k_scan1(int n, int nb) {
    __shared__ int wsum[8];
    __shared__ int is_last;
    int i = blockIdx.x * SCAN_B + threadIdx.x;
    int lane = threadIdx.x & 31, wid = threadIdx.x >> 5;
    if (i < n) g_tmp[i] = 0;
    int v = (i < n) ? g_deg[i] + 1 : 0;     // +1 = self-loop
    int x = warp_incl_scan(v);
    if (lane == 31) wsum[wid] = x;
    __syncthreads();
    if (wid == 0) {
        int y = (lane < 8) ? wsum[lane] : 0;
#pragma unroll
        for (int o = 1; o < 8; o <<= 1) {
            int t = __shfl_up_sync(0xffffffffu, y, o);
            if (lane >= o) y += t;
        }
        if (lane < 8) wsum[lane] = y;
    }
    __syncthreads();
    int excl = x - v + (wid > 0 ? wsum[wid - 1] : 0);
    if (i <= n) g_rowptr[i] = excl;
    if (threadIdx.x == 0) g_bsum[blockIdx.x] = wsum[7];

    __threadfence();
    if (threadIdx.x == 0) {
        int t = atomicAdd(&g_arrive, 1);
        is_last = (t == gridDim.x - 1);
    }
    __syncthreads();
    if (is_last) {
        int tt = threadIdx.x;
        int vv = (tt < nb) ? g_bsum[tt] : 0;
        int xx = warp_incl_scan(vv);
        if (lane == 31) wsum[wid] = xx;
        __syncthreads();
        if (wid == 0) {
            int y = (lane < 8) ? wsum[lane] : 0;
#pragma unroll
            for (int o = 1; o < 8; o <<= 1) {
                int t2 = __shfl_up_sync(0xffffffffu, y, o);
                if (lane >= o) y += t2;
            }
            if (lane < 8) wsum[lane] = y;
        }
        __syncthreads();
        int ex2 = xx - vv + (wid > 0 ? wsum[wid - 1] : 0);
        if (tt < nb) g_boff[tt] = ex2;
        if (tt == 0) g_arrive = 0;
    }
}

// ================= scatter (edges then self-loops) =================
__global__ void k_scatter(const void* __restrict__ ei, int E, int n) {
    long long e0 = (long long)blockIdx.x * 256;
    bool is64 = block_detect_is64((const int*)ei, e0, E);
    long long i = e0 + threadIdx.x;
    int s, d;
    if (i < E) {
        d = load_edge(ei, is64, (size_t)E + i);
        if ((unsigned)d >= (unsigned)n) return;
        s = load_edge(ei, is64, (size_t)i);
        if ((unsigned)s >= (unsigned)n) s = 0;
    } else if (i < E + n) {
        s = d = (int)(i - E);
    } else return;
    int pos = rowp(d) + atomicAdd(&g_tmp[d], 1);
    g_col[pos] = s;
}

// ================= layer-1 edge softmax + aggregate + bias + elu =================
// (R14 shape: 2 dst/warp, 4 edges/iter, validity-masked)
__global__ __launch_bounds__(256) void agg1(const float* __restrict__ bias1, int n) {
    int gwarp = (blockIdx.x * blockDim.x + threadIdx.x) >> 5;
    int lane  = threadIdx.x & 31;
    int half  = lane >> 4;
    int hl    = lane & 15;
    int half0 = half << 4;
    int nd = gwarp * 2 + half;
    bool okn = nd < n;
    int ndc = okn ? nd : 0;
    int h    = hl & 7;
    int j    = hl >> 3;
    int hown = hl >> 1;

    float adv = g_adst1[ndc * HEADS + h];
    int beg = rowp(ndc);
    int end = okn ? rowp(ndc + 1) : beg;

    ull acc01 = 0ull, acc23 = 0ull;
    float den = 0.f;

    int iters = (end - beg + 3) >> 2;
    int oth = __shfl_xor_sync(0xffffffffu, iters, 16);
    int mx = iters > oth ? iters : oth;

    for (int k = 0; k < mx; k++) {
        int e0 = beg + 4 * k;
        bool v0 = e0 < end, v1 = e0 + 1 < end, v2 = e0 + 2 < end, v3 = e0 + 3 < end;
        int s0 = g_col[v0 ? e0     : beg];
        int s1 = g_col[v1 ? e0 + 1 : beg];
        int s2 = g_col[v2 ? e0 + 2 : beg];
        int s3 = g_col[v3 ? e0 + 3 : beg];
        int sa = j ? s1 : s0;
        int sb = j ? s3 : s2;
        float aa = g_asrc1[sa * HEADS + h] + adv;
        float ab = g_asrc1[sb * HEADS + h] + adv;
        ulonglong2 u0 = *(const ulonglong2*)&g_h1[(size_t)s0 * C1 + 4 * hl];
        ulonglong2 u1 = *(const ulonglong2*)&g_h1[(size_t)s1 * C1 + 4 * hl];
        ulonglong2 u2 = *(const ulonglong2*)&g_h1[(size_t)s2 * C1 + 4 * hl];
        ulonglong2 u3 = *(const ulonglong2*)&g_h1[(size_t)s3 * C1 + 4 * hl];
        aa = aa > 0.f ? aa : 0.2f * aa;
        ab = ab > 0.f ? ab : 0.2f * ab;
        float wa = __expf(aa);
        float wb = __expf(ab);
        wa = (j ? v1 : v0) ? wa : 0.f;
        wb = (j ? v3 : v2) ? wb : 0.f;
        den += wa + wb;
        float w0o = __shfl_sync(0xffffffffu, wa, half0 + hown);
        float w1o = __shfl_sync(0xffffffffu, wa, half0 + 8 + hown);
        float w2o = __shfl_sync(0xffffffffu, wb, half0 + hown);
        float w3o = __shfl_sync(0xffffffffu, wb, half0 + 8 + hown);
        ull wp0, wp1, wp2, wp3;
        PACK_DUP_F32X2(wp0, w0o);
        PACK_DUP_F32X2(wp1, w1o);
        PACK_DUP_F32X2(wp2, w2o);
        PACK_DUP_F32X2(wp3, w3o);
        FMA_F32X2(acc01, wp0, u0.x, acc01);
        FMA_F32X2(acc23, wp0, u0.y, acc23);
        FMA_F32X2(acc01, wp1, u1.x, acc01);
        FMA_F32X2(acc23, wp1, u1.y, acc23);
        FMA_F32X2(acc01, wp2, u2.x, acc01);
        FMA_F32X2(acc23, wp2, u2.y, acc23);
        FMA_F32X2(acc01, wp3, u3.x, acc01);
        FMA_F32X2(acc23, wp3, u3.y, acc23);
    }

    den += __shfl_xor_sync(0xffffffffu, den, 8);
    float deno = __shfl_sync(0xffffffffu, den, half0 + hown);

    if (okn) {
        uint2 ua = *(uint2*)&acc01;
        uint2 ub = *(uint2*)&acc23;
        float4 bv = *(const float4*)&bias1[4 * hl];
        float o0 = __uint_as_float(ua.x) / deno + bv.x;
        float o1 = __uint_as_float(ua.y) / deno + bv.y;
        float o2 = __uint_as_float(ub.x) / deno + bv.z;
        float o3 = __uint_as_float(ub.y) / deno + bv.w;
        o0 = o0 > 0.f ? o0 : expm1f(o0);
        o1 = o1 > 0.f ? o1 : expm1f(o1);
        o2 = o2 > 0.f ? o2 : expm1f(o2);
        o3 = o3 > 0.f ? o3 : expm1f(o3);
        *(float4*)&g_h1act[(size_t)nd * C1 + 4 * hl] = make_float4(o0, o1, o2, o3);
    }
}

// ================= GEMM2: h2 = h1act @ W2, fused scalar logits =================
__global__ __launch_bounds__(256) void gemm2(
    const float* __restrict__ W2, const float* __restrict__ aS,
    const float* __restrict__ aD, int n)
{
    __shared__ float ws[64 * 16];
    int tid = threadIdx.x;
    for (int i = tid; i < 64 * 16; i += 256) ws[i] = W2[i];
    __syncthreads();

    int warp = tid >> 5, lane = tid & 31;
    int row0 = (blockIdx.x * 8 + warp) * 2 + (lane >> 4);
    int c = lane & 15;
    bool ok = row0 < n;
    int row = ok ? row0 : 0;

    float xr[4];
#pragma unroll
    for (int j = 0; j < 4; j++) xr[j] = g_h1act[(size_t)row * C1 + c + 16 * j];

    float acc = 0.f;
#pragma unroll
    for (int k = 0; k < 64; k++) {
        float xk = __shfl_sync(0xffffffffu, xr[k >> 4], (lane & 16) | (k & 15));
        acc = fmaf(xk, ws[k * 16 + c], acc);
    }

    float ts = acc * aS[c];
    float td = acc * aD[c];
#pragma unroll
    for (int off = 8; off >= 1; off >>= 1) {
        ts += __shfl_xor_sync(0xffffffffu, ts, off);
        td += __shfl_xor_sync(0xffffffffu, td, off);
    }
    if (ok) {
        g_h2[(size_t)row * CLS + c] = acc;
        if (c == 0) { g_asrc2[row] = ts; g_adst2[row] = td; }
    }
}

// ================= layer-2 aggregate + bias + log_softmax (R13 shape) =================
__global__ __launch_bounds__(256) void agg2(
    const float* __restrict__ bias2, float* __restrict__ out, int n)
{
    int warp = (blockIdx.x * blockDim.x + threadIdx.x) >> 5;
    int lane = threadIdx.x & 31;
    int node0 = warp * 2 + (lane >> 4);
    int c = lane & 15;
    bool ok = node0 < n;
    int nd = ok ? node0 : 0;

    float adv = g_adst2[nd];
    int beg = rowp(nd);
    int end = ok ? rowp(nd + 1) : beg;
    float acc = 0.f, den = 0.f;
    int e = beg;
    for (; e + 2 <= end; e += 2) {
        int s0 = g_col[e], s1 = g_col[e + 1];
        float a0 = g_asrc2[s0] + adv;
        float a1 = g_asrc2[s1] + adv;
        float f0 = g_h2[(size_t)s0 * CLS + c];
        float f1 = g_h2[(size_t)s1 * CLS + c];
        a0 = a0 > 0.f ? a0 : 0.2f * a0;
        a1 = a1 > 0.f ? a1 : 0.2f * a1;
        float w0 = __expf(a0), w1 = __expf(a1);
        den += w0 + w1;
        acc = fmaf(w0, f0, acc);
        acc = fmaf(w1, f1, acc);
    }
    if (e < end) {
        int s0 = g_col[e];
        float a0 = g_asrc2[s0] + adv;
        a0 = a0 > 0.f ? a0 : 0.2f * a0;
        float w0 = __expf(a0);
        den += w0;
        acc = fmaf(w0, g_h2[(size_t)s0 * CLS + c], acc);
    }
    float val = ok ? (acc / den + bias2[c]) : 0.f;
    float m = val;
#pragma unroll
    for (int off = 8; off >= 1; off >>= 1)
        m = fmaxf(m, __shfl_xor_sync(0xffffffffu, m, off));
    float ex = __expf(val - m);
    float s = ex;
#pragma unroll
    for (int off = 8; off >= 1; off >>= 1)
        s += __shfl_xor_sync(0xffffffffu, s, off);
    if (ok) out[(size_t)node0 * CLS + c] = val - m - __logf(s);
}

// ---------------- launch ----------------
extern "C" void kernel_launch(void* const* d_in, const int* in_sizes, int n_in,
                              void* d_out, int out_size) {
    const float* x     = (const float*)d_in[0];
    const void*  ei    = d_in[1];
    const float* W1    = (const float*)d_in[2];
    const float* attS1 = (const float*)d_in[3];
    const float* attD1 = (const float*)d_in[4];
    const float* bias1 = (const float*)d_in[5];
    const float* W2    = (const float*)d_in[6];
    const float* attS2 = (const float*)d_in[7];
    const float* attD2 = (const float*)d_in[8];
    const float* bias2 = (const float*)d_in[9];
    float* out = (float*)d_out;

    int n = in_sizes[0] / F_IN;      // 50000
    int E = in_sizes[1] / 2;         // 1600000

    void* p_deg = nullptr;
    cudaGetSymbolAddress(&p_deg, g_deg);
    cudaMemsetAsync(p_deg, 0, (size_t)n * sizeof(int));

    int GB = (n + 127) / 128;                 // gemm1 blocks (391, 128-row tiles)
    int CB = (E + 255) / 256;                 // count blocks (6250)
    int nb = (n + SCAN_B - 1) / SCAN_B;       // scan blocks (196)
    int AW = (n + 1) / 2;                     // 2-node warps (agg1)

    k_gemm1_count<<<GB + CB, 256>>>(x, W1, attS1, attD1, ei, n, E, GB);
    k_scan1<<<nb, SCAN_B>>>(n, nb);
    k_scatter<<<(E + n + 255) / 256, 256>>>(ei, E, n);
    agg1 <<<(AW + 7) / 8, 256>>>(bias1, n);     // <- ncu lands here
    gemm2<<<(n + 15) / 16, 256>>>(W2, attS2, attD2, n);
    agg2 <<<(n + 15) / 16, 256>>>(bias2, out, n);
}

// round 16
// speedup vs baseline: 1.3199x; 1.0188x over previous
#include <cuda_runtime.h>
#include <cuda_fp16.h>
#include <cstdint>

#define MAXN 50000
#define MAXE 1600000
#define F_IN 512
#define C1 64      // heads*hid = 8*8
#define HEADS 8
#define CLS 16
#define SCAN_B 256

typedef unsigned long long ull;

// packed fp32x2 FMA (sm_103a)
#define FMA_F32X2(d, a, b, c) \
    asm("fma.rn.f32x2 %0, %1, %2, %3;" : "=l"(d) : "l"(a), "l"(b), "l"(c))
#define PACK_DUP_F32X2(d, f) \
    asm("mov.b64 %0, {%1, %1};" : "=l"(d) : "r"(__float_as_uint(f)))

#define MMA16816(d0,d1,d2,d3,a0,a1,a2,a3,b0,b1) \
    asm volatile("mma.sync.aligned.m16n8k16.row.col.f32.f16.f16.f32 " \
        "{%0,%1,%2,%3}, {%4,%5,%6,%7}, {%8,%9}, {%0,%1,%2,%3};" \
        : "+f"(d0), "+f"(d1), "+f"(d2), "+f"(d3) \
        : "r"(a0), "r"(a1), "r"(a2), "r"(a3), "r"(b0), "r"(b1))

// ---------------- scratch ----------------
__device__ __align__(16) int   g_deg[MAXN];        // zeroed via cudaMemsetAsync
__device__ __align__(16) int   g_tmp[MAXN];        // zeroed inside k_scan1
__device__ __align__(16) int   g_rowptr[MAXN + 1]; // block-local exclusive prefix
__device__ __align__(16) int   g_bsum[256];
__device__ __align__(16) int   g_boff[256];        // per-block offset
__device__            int      g_arrive = 0;       // last-block ticket (returns to 0)
__device__ __align__(16) int   g_col[MAXE + MAXN + 8];
__device__ __align__(16) float g_h1[(size_t)MAXN * C1];
__device__ __align__(16) float g_asrc1[MAXN * HEADS];
__device__ __align__(16) float g_adst1[MAXN * HEADS];
__device__ __align__(16) float g_h1act[(size_t)MAXN * C1];
__device__ __align__(16) float g_h2[(size_t)MAXN * CLS];
__device__ __align__(16) float g_asrc2[MAXN];
__device__ __align__(16) float g_adst2[MAXN];

__device__ __forceinline__ int rowp(int i) {
    return g_rowptr[i] + g_boff[i >> 8];
}

__device__ __forceinline__ bool block_detect_is64(const int* w32, long long e0, int E) {
    int hi = 0;
    long long e = e0 + threadIdx.x;
    if (e < E) hi = w32[2 * e + 1];
    return !__syncthreads_or(hi != 0);
}

__device__ __forceinline__ int load_edge(const void* ei, bool is64, size_t pos) {
    return is64 ? (int)((const long long*)ei)[pos] : ((const int*)ei)[pos];
}

// ================= fused GEMM1 (fp16 HMMA) + edge count =================
// blocks [0, GB): gemm1 tiles of 128 rows x 64 cols; blocks [GB,...): degree count
// Strides 40 halfs (80B = 20 words): bank-conflict-free fragment access
// (banks 20*lq % 32 = {0,20,8,28,16,4,24,12}, x4 lr offsets -> all 32 distinct).
#define XSS 40   // xs row stride (halfs)
#define WSS 40   // wsT row stride (halfs)
__global__ __launch_bounds__(256) void k_gemm1_count(
    const float* __restrict__ x, const float* __restrict__ W,
    const float* __restrict__ attS, const float* __restrict__ attD,
    const void* __restrict__ ei, int n, int E, int GB)
{
    if (blockIdx.x >= GB) {
        long long e0 = (long long)(blockIdx.x - GB) * 256;
        bool is64 = block_detect_is64((const int*)ei, e0, E);
        long long e = e0 + threadIdx.x;
        if (e < E) {
            int d = load_edge(ei, is64, (size_t)E + e);
            if ((unsigned)d < (unsigned)n) atomicAdd(&g_deg[d], 1);
        }
        return;
    }

    __shared__ __align__(16) __half xs[128 * XSS];   // [row][k] halfs
    __shared__ __align__(16) __half wsT[64 * WSS];   // [n][k]   halfs (transposed W)
    int tid = threadIdx.x;
    int w = tid >> 5, lane = tid & 31;
    int r0 = blockIdx.x * 128;
    int lq = lane >> 2;        // 0..7
    int lr = lane & 3;         // 0..3

    float acc[8][4];
#pragma unroll
    for (int t = 0; t < 8; t++)
#pragma unroll
        for (int q = 0; q < 4; q++) acc[t][q] = 0.f;

    for (int kc = 0; kc < F_IN; kc += 32) {
        // x tile 128x32 fp32 -> fp16 smem
#pragma unroll
        for (int i = 0; i < 4; i++) {
            int idx = tid + 256 * i;       // 1024 float4
            int row = idx >> 3;
            int q   = idx & 7;
            float4 v = make_float4(0.f, 0.f, 0.f, 0.f);
            int gr = r0 + row;
            if (gr < n) v = *(const float4*)&x[(size_t)gr * F_IN + kc + q * 4];
            __half2 h01 = __floats2half2_rn(v.x, v.y);
            __half2 h23 = __floats2half2_rn(v.z, v.w);
            uint2 pv;
            pv.x = *(unsigned*)&h01; pv.y = *(unsigned*)&h23;
            *(uint2*)&xs[row * XSS + q * 4] = pv;    // 80*row+8q bytes: 8B aligned
        }
        // W tile 32x64 fp32 -> transposed fp16 smem wsT[n][k]
#pragma unroll
        for (int i = 0; i < 2; i++) {
            int idx = tid + 256 * i;       // 512 float4
            int k  = idx >> 4;
            int c4 = (idx & 15) * 4;
            float4 v = *(const float4*)&W[(size_t)(kc + k) * C1 + c4];
            wsT[(c4 + 0) * WSS + k] = __float2half_rn(v.x);
            wsT[(c4 + 1) * WSS + k] = __float2half_rn(v.y);
            wsT[(c4 + 2) * WSS + k] = __float2half_rn(v.z);
            wsT[(c4 + 3) * WSS + k] = __float2half_rn(v.w);
        }
        __syncthreads();
#pragma unroll
        for (int s = 0; s < 2; s++) {      // two k16 steps
            int r  = w * 16 + lq;
            int kb = s * 16 + lr * 2;
            unsigned a0 = *(const unsigned*)&xs[r * XSS + kb];
            unsigned a1 = *(const unsigned*)&xs[(r + 8) * XSS + kb];
            unsigned a2 = *(const unsigned*)&xs[r * XSS + kb + 8];
            unsigned a3 = *(const unsigned*)&xs[(r + 8) * XSS + kb + 8];
#pragma unroll
            for (int t = 0; t < 8; t++) {
                int nn = t * 8 + lq;
                unsigned b0 = *(const unsigned*)&wsT[nn * WSS + kb];
                unsigned b1 = *(const unsigned*)&wsT[nn * WSS + kb + 8];
                MMA16816(acc[t][0], acc[t][1], acc[t][2], acc[t][3],
                         a0, a1, a2, a3, b0, b1);
            }
        }
        __syncthreads();
    }

    // epilogue: lane holds rows (gra, grb), cols 8t+c0, 8t+c0+1 per tile t (t == head)
    int c0 = 2 * lr;
    int gra = r0 + w * 16 + lq;
    int grb = gra + 8;
    bool oka = gra < n, okb = grb < n;
#pragma unroll
    for (int t = 0; t < 8; t++) {
        float e0 = __ldg(&attS[8 * t + c0]);
        float e1 = __ldg(&attS[8 * t + c0 + 1]);
        float f0 = __ldg(&attD[8 * t + c0]);
        float f1 = __ldg(&attD[8 * t + c0 + 1]);
        float sa = fmaf(acc[t][0], e0, acc[t][1] * e1);
        float da = fmaf(acc[t][0], f0, acc[t][1] * f1);
        float sb = fmaf(acc[t][2], e0, acc[t][3] * e1);
        float db = fmaf(acc[t][2], f0, acc[t][3] * f1);
        sa += __shfl_xor_sync(0xffffffffu, sa, 1);
        sa += __shfl_xor_sync(0xffffffffu, sa, 2);
        da += __shfl_xor_sync(0xffffffffu, da, 1);
        da += __shfl_xor_sync(0xffffffffu, da, 2);
        sb += __shfl_xor_sync(0xffffffffu, sb, 1);
        sb += __shfl_xor_sync(0xffffffffu, sb, 2);
        db += __shfl_xor_sync(0xffffffffu, db, 1);
        db += __shfl_xor_sync(0xffffffffu, db, 2);
        if (oka) {
            *(float2*)&g_h1[(size_t)gra * C1 + 8 * t + c0] = make_float2(acc[t][0], acc[t][1]);
            if (lr == 0) { g_asrc1[gra * HEADS + t] = sa; g_adst1[gra * HEADS + t] = da; }
        }
        if (okb) {
            *(float2*)&g_h1[(size_t)grb * C1 + 8 * t + c0] = make_float2(acc[t][2], acc[t][3]);
            if (lr == 0) { g_asrc1[grb * HEADS + t] = sb; g_adst1[grb * HEADS + t] = db; }
        }
    }
}

// ================= single-pass block scan (last block folds scan2) =================
__device__ __forceinline__ int warp_incl_scan(int x) {
#pragma unroll
    for (int o = 1; o < 32; o <<= 1) {
        int t = __shfl_up_sync(0xffffffffu, x, o);
        if ((threadIdx.x & 31) >= o) x += t;
    }
    return x;
}

__global__ void k_scan1(int n, int nb) {
    __shared__ int wsum[8];
    __shared__ int is_last;
    int i = blockIdx.x * SCAN_B + threadIdx.x;
    int lane = threadIdx.x & 31, wid = threadIdx.x >> 5;
    if (i < n) g_tmp[i] = 0;
    int v = (i < n) ? g_deg[i] + 1 : 0;     // +1 = self-loop
    int x = warp_incl_scan(v);
    if (lane == 31) wsum[wid] = x;
    __syncthreads();
    if (wid == 0) {
        int y = (lane < 8) ? wsum[lane] : 0;
#pragma unroll
        for (int o = 1; o < 8; o <<= 1) {
            int t = __shfl_up_sync(0xffffffffu, y, o);
            if (lane >= o) y += t;
        }
        if (lane < 8) wsum[lane] = y;
    }
    __syncthreads();
    int excl = x - v + (wid > 0 ? wsum[wid - 1] : 0);
    if (i <= n) g_rowptr[i] = excl;
    if (threadIdx.x == 0) g_bsum[blockIdx.x] = wsum[7];

    __threadfence();
    if (threadIdx.x == 0) {
        int t = atomicAdd(&g_arrive, 1);
        is_last = (t == gridDim.x - 1);
    }
    __syncthreads();
    if (is_last) {
        int tt = threadIdx.x;
        int vv = (tt < nb) ? g_bsum[tt] : 0;
        int xx = warp_incl_scan(vv);
        if (lane == 31) wsum[wid] = xx;
        __syncthreads();
        if (wid == 0) {
            int y = (lane < 8) ? wsum[lane] : 0;
#pragma unroll
            for (int o = 1; o < 8; o <<= 1) {
                int t2 = __shfl_up_sync(0xffffffffu, y, o);
                if (lane >= o) y += t2;
            }
            if (lane < 8) wsum[lane] = y;
        }
        __syncthreads();
        int ex2 = xx - vv + (wid > 0 ? wsum[wid - 1] : 0);
        if (tt < nb) g_boff[tt] = ex2;
        if (tt == 0) g_arrive = 0;
    }
}

// ================= scatter (edges then self-loops) =================
__global__ void k_scatter(const void* __restrict__ ei, int E, int n) {
    long long e0 = (long long)blockIdx.x * 256;
    bool is64 = block_detect_is64((const int*)ei, e0, E);
    long long i = e0 + threadIdx.x;
    int s, d;
    if (i < E) {
        d = load_edge(ei, is64, (size_t)E + i);
        if ((unsigned)d >= (unsigned)n) return;
        s = load_edge(ei, is64, (size_t)i);
        if ((unsigned)s >= (unsigned)n) s = 0;
    } else if (i < E + n) {
        s = d = (int)(i - E);
    } else return;
    int pos = rowp(d) + atomicAdd(&g_tmp[d], 1);
    g_col[pos] = s;
}

// ================= layer-1 edge softmax + aggregate + bias + elu =================
// (R14 shape: 2 dst/warp, 4 edges/iter, validity-masked)
__global__ __launch_bounds__(256) void agg1(const float* __restrict__ bias1, int n) {
    int gwarp = (blockIdx.x * blockDim.x + threadIdx.x) >> 5;
    int lane  = threadIdx.x & 31;
    int half  = lane >> 4;
    int hl    = lane & 15;
    int half0 = half << 4;
    int nd = gwarp * 2 + half;
    bool okn = nd < n;
    int ndc = okn ? nd : 0;
    int h    = hl & 7;
    int j    = hl >> 3;
    int hown = hl >> 1;

    float adv = g_adst1[ndc * HEADS + h];
    int beg = rowp(ndc);
    int end = okn ? rowp(ndc + 1) : beg;

    ull acc01 = 0ull, acc23 = 0ull;
    float den = 0.f;

    int iters = (end - beg + 3) >> 2;
    int oth = __shfl_xor_sync(0xffffffffu, iters, 16);
    int mx = iters > oth ? iters : oth;

    for (int k = 0; k < mx; k++) {
        int e0 = beg + 4 * k;
        bool v0 = e0 < end, v1 = e0 + 1 < end, v2 = e0 + 2 < end, v3 = e0 + 3 < end;
        int s0 = g_col[v0 ? e0     : beg];
        int s1 = g_col[v1 ? e0 + 1 : beg];
        int s2 = g_col[v2 ? e0 + 2 : beg];
        int s3 = g_col[v3 ? e0 + 3 : beg];
        int sa = j ? s1 : s0;
        int sb = j ? s3 : s2;
        float aa = g_asrc1[sa * HEADS + h] + adv;
        float ab = g_asrc1[sb * HEADS + h] + adv;
        ulonglong2 u0 = *(const ulonglong2*)&g_h1[(size_t)s0 * C1 + 4 * hl];
        ulonglong2 u1 = *(const ulonglong2*)&g_h1[(size_t)s1 * C1 + 4 * hl];
        ulonglong2 u2 = *(const ulonglong2*)&g_h1[(size_t)s2 * C1 + 4 * hl];
        ulonglong2 u3 = *(const ulonglong2*)&g_h1[(size_t)s3 * C1 + 4 * hl];
        aa = aa > 0.f ? aa : 0.2f * aa;
        ab = ab > 0.f ? ab : 0.2f * ab;
        float wa = __expf(aa);
        float wb = __expf(ab);
        wa = (j ? v1 : v0) ? wa : 0.f;
        wb = (j ? v3 : v2) ? wb : 0.f;
        den += wa + wb;
        float w0o = __shfl_sync(0xffffffffu, wa, half0 + hown);
        float w1o = __shfl_sync(0xffffffffu, wa, half0 + 8 + hown);
        float w2o = __shfl_sync(0xffffffffu, wb, half0 + hown);
        float w3o = __shfl_sync(0xffffffffu, wb, half0 + 8 + hown);
        ull wp0, wp1, wp2, wp3;
        PACK_DUP_F32X2(wp0, w0o);
        PACK_DUP_F32X2(wp1, w1o);
        PACK_DUP_F32X2(wp2, w2o);
        PACK_DUP_F32X2(wp3, w3o);
        FMA_F32X2(acc01, wp0, u0.x, acc01);
        FMA_F32X2(acc23, wp0, u0.y, acc23);
        FMA_F32X2(acc01, wp1, u1.x, acc01);
        FMA_F32X2(acc23, wp1, u1.y, acc23);
        FMA_F32X2(acc01, wp2, u2.x, acc01);
        FMA_F32X2(acc23, wp2, u2.y, acc23);
        FMA_F32X2(acc01, wp3, u3.x, acc01);
        FMA_F32X2(acc23, wp3, u3.y, acc23);
    }

    den += __shfl_xor_sync(0xffffffffu, den, 8);
    float deno = __shfl_sync(0xffffffffu, den, half0 + hown);

    if (okn) {
        uint2 ua = *(uint2*)&acc01;
        uint2 ub = *(uint2*)&acc23;
        float4 bv = *(const float4*)&bias1[4 * hl];
        float o0 = __uint_as_float(ua.x) / deno + bv.x;
        float o1 = __uint_as_float(ua.y) / deno + bv.y;
        float o2 = __uint_as_float(ub.x) / deno + bv.z;
        float o3 = __uint_as_float(ub.y) / deno + bv.w;
        o0 = o0 > 0.f ? o0 : expm1f(o0);
        o1 = o1 > 0.f ? o1 : expm1f(o1);
        o2 = o2 > 0.f ? o2 : expm1f(o2);
        o3 = o3 > 0.f ? o3 : expm1f(o3);
        *(float4*)&g_h1act[(size_t)nd * C1 + 4 * hl] = make_float4(o0, o1, o2, o3);
    }
}

// ================= GEMM2: h2 = h1act @ W2, fused scalar logits =================
__global__ __launch_bounds__(256) void gemm2(
    const float* __restrict__ W2, const float* __restrict__ aS,
    const float* __restrict__ aD, int n)
{
    __shared__ float ws[64 * 16];
    int tid = threadIdx.x;
    for (int i = tid; i < 64 * 16; i += 256) ws[i] = W2[i];
    __syncthreads();

    int warp = tid >> 5, lane = tid & 31;
    int row0 = (blockIdx.x * 8 + warp) * 2 + (lane >> 4);
    int c = lane & 15;
    bool ok = row0 < n;
    int row = ok ? row0 : 0;

    float xr[4];
#pragma unroll
    for (int j = 0; j < 4; j++) xr[j] = g_h1act[(size_t)row * C1 + c + 16 * j];

    float acc = 0.f;
#pragma unroll
    for (int k = 0; k < 64; k++) {
        float xk = __shfl_sync(0xffffffffu, xr[k >> 4], (lane & 16) | (k & 15));
        acc = fmaf(xk, ws[k * 16 + c], acc);
    }

    float ts = acc * aS[c];
    float td = acc * aD[c];
#pragma unroll
    for (int off = 8; off >= 1; off >>= 1) {
        ts += __shfl_xor_sync(0xffffffffu, ts, off);
        td += __shfl_xor_sync(0xffffffffu, td, off);
    }
    if (ok) {
        g_h2[(size_t)row * CLS + c] = acc;
        if (c == 0) { g_asrc2[row] = ts; g_adst2[row] = td; }
    }
}

// ================= layer-2 aggregate + bias + log_softmax (R13 shape) =================
__global__ __launch_bounds__(256) void agg2(
    const float* __restrict__ bias2, float* __restrict__ out, int n)
{
    int warp = (blockIdx.x * blockDim.x + threadIdx.x) >> 5;
    int lane = threadIdx.x & 31;
    int node0 = warp * 2 + (lane >> 4);
    int c = lane & 15;
    bool ok = node0 < n;
    int nd = ok ? node0 : 0;

    float adv = g_adst2[nd];
    int beg = rowp(nd);
    int end = ok ? rowp(nd + 1) : beg;
    float acc = 0.f, den = 0.f;
    int e = beg;
    for (; e + 2 <= end; e += 2) {
        int s0 = g_col[e], s1 = g_col[e + 1];
        float a0 = g_asrc2[s0] + adv;
        float a1 = g_asrc2[s1] + adv;
        float f0 = g_h2[(size_t)s0 * CLS + c];
        float f1 = g_h2[(size_t)s1 * CLS + c];
        a0 = a0 > 0.f ? a0 : 0.2f * a0;
        a1 = a1 > 0.f ? a1 : 0.2f * a1;
        float w0 = __expf(a0), w1 = __expf(a1);
        den += w0 + w1;
        acc = fmaf(w0, f0, acc);
        acc = fmaf(w1, f1, acc);
    }
    if (e < end) {
        int s0 = g_col[e];
        float a0 = g_asrc2[s0] + adv;
        a0 = a0 > 0.f ? a0 : 0.2f * a0;
        float w0 = __expf(a0);
        den += w0;
        acc = fmaf(w0, g_h2[(size_t)s0 * CLS + c], acc);
    }
    float val = ok ? (acc / den + bias2[c]) : 0.f;
    float m = val;
#pragma unroll
    for (int off = 8; off >= 1; off >>= 1)
        m = fmaxf(m, __shfl_xor_sync(0xffffffffu, m, off));
    float ex = __expf(val - m);
    float s = ex;
#pragma unroll
    for (int off = 8; off >= 1; off >>= 1)
        s += __shfl_xor_sync(0xffffffffu, s, off);
    if (ok) out[(size_t)node0 * CLS + c] = val - m - __logf(s);
}

// ---------------- launch ----------------
extern "C" void kernel_launch(void* const* d_in, const int* in_sizes, int n_in,
                              void* d_out, int out_size) {
    const float* x     = (const float*)d_in[0];
    const void*  ei    = d_in[1];
    const float* W1    = (const float*)d_in[2];
    const float* attS1 = (const float*)d_in[3];
    const float* attD1 = (const float*)d_in[4];
    const float* bias1 = (const float*)d_in[5];
    const float* W2    = (const float*)d_in[6];
    const float* attS2 = (const float*)d_in[7];
    const float* attD2 = (const float*)d_in[8];
    const float* bias2 = (const float*)d_in[9];
    float* out = (float*)d_out;

    int n = in_sizes[0] / F_IN;      // 50000
    int E = in_sizes[1] / 2;         // 1600000

    void* p_deg = nullptr;
    cudaGetSymbolAddress(&p_deg, g_deg);
    cudaMemsetAsync(p_deg, 0, (size_t)n * sizeof(int));

    int GB = (n + 127) / 128;                 // gemm1 blocks (391, 128-row tiles)
    int CB = (E + 255) / 256;                 // count blocks (6250)
    int nb = (n + SCAN_B - 1) / SCAN_B;       // scan blocks (196)
    int AW = (n + 1) / 2;                     // 2-node warps (agg1)

    k_gemm1_count<<<GB + CB, 256>>>(x, W1, attS1, attD1, ei, n, E, GB);
    k_scan1<<<nb, SCAN_B>>>(n, nb);
    k_scatter<<<(E + n + 255) / 256, 256>>>(ei, E, n);
    agg1 <<<(AW + 7) / 8, 256>>>(bias1, n);     // <- ncu lands here
    gemm2<<<(n + 15) / 16, 256>>>(W2, attS2, attD2, n);
    agg2 <<<(n + 15) / 16, 256>>>(bias2, out, n);
}

// round 17
// speedup vs baseline: 1.3745x; 1.0414x over previous
#include <cuda_runtime.h>
#include <cuda_fp16.h>
#include <cstdint>

#define MAXN 50000
#define MAXE 1600000
#define F_IN 512
#define C1 64      // heads*hid = 8*8
#define HEADS 8
#define CLS 16
#define SCAN_B 256

typedef unsigned long long ull;

// packed fp32x2 FMA (sm_103a)
#define FMA_F32X2(d, a, b, c) \
    asm("fma.rn.f32x2 %0, %1, %2, %3;" : "=l"(d) : "l"(a), "l"(b), "l"(c))
#define PACK_DUP_F32X2(d, f) \
    asm("mov.b64 %0, {%1, %1};" : "=l"(d) : "r"(__float_as_uint(f)))

#define MMA16816(d0,d1,d2,d3,a0,a1,a2,a3,b0,b1) \
    asm volatile("mma.sync.aligned.m16n8k16.row.col.f32.f16.f16.f32 " \
        "{%0,%1,%2,%3}, {%4,%5,%6,%7}, {%8,%9}, {%0,%1,%2,%3};" \
        : "+f"(d0), "+f"(d1), "+f"(d2), "+f"(d3) \
        : "r"(a0), "r"(a1), "r"(a2), "r"(a3), "r"(b0), "r"(b1))

// ---------------- scratch ----------------
__device__ __align__(16) int   g_deg[MAXN];        // zeroed via cudaMemsetAsync
__device__ __align__(16) int   g_tmp[MAXN];        // zeroed inside k_scan1
__device__ __align__(16) int   g_rowptr[MAXN + 1]; // block-local exclusive prefix
__device__ __align__(16) int   g_bsum[256];
__device__ __align__(16) int   g_boff[256];        // per-block offset
__device__            int      g_arrive = 0;       // last-block ticket (returns to 0)
__device__ __align__(16) int   g_col[MAXE + MAXN + 8];
__device__ __align__(16) float g_h1[(size_t)MAXN * C1];
__device__ __align__(16) float g_asrc1[MAXN * HEADS];
__device__ __align__(16) float g_adst1[MAXN * HEADS];
__device__ __align__(16) float g_h1act[(size_t)MAXN * C1];
__device__ __align__(16) float g_h2[(size_t)MAXN * CLS];
__device__ __align__(16) float g_asrc2[MAXN];
__device__ __align__(16) float g_adst2[MAXN];

__device__ __forceinline__ int rowp(int i) {
    return g_rowptr[i] + g_boff[i >> 8];
}

__device__ __forceinline__ bool block_detect_is64(const int* w32, long long e0, int E) {
    int hi = 0;
    long long e = e0 + threadIdx.x;
    if (e < E) hi = w32[2 * e + 1];
    return !__syncthreads_or(hi != 0);
}

__device__ __forceinline__ int load_edge(const void* ei, bool is64, size_t pos) {
    return is64 ? (int)((const long long*)ei)[pos] : ((const int*)ei)[pos];
}

// ================= fused GEMM1 (fp16 HMMA) + edge count =================
// Strides 40 halfs (80B): bank-conflict-free fragment access.
#define XSS 40
#define WSS 40
__global__ __launch_bounds__(256) void k_gemm1_count(
    const float* __restrict__ x, const float* __restrict__ W,
    const float* __restrict__ attS, const float* __restrict__ attD,
    const void* __restrict__ ei, int n, int E, int GB)
{
    if (blockIdx.x >= GB) {
        long long e0 = (long long)(blockIdx.x - GB) * 256;
        bool is64 = block_detect_is64((const int*)ei, e0, E);
        long long e = e0 + threadIdx.x;
        if (e < E) {
            int d = load_edge(ei, is64, (size_t)E + e);
            if ((unsigned)d < (unsigned)n) atomicAdd(&g_deg[d], 1);
        }
        return;
    }

    __shared__ __align__(16) __half xs[128 * XSS];
    __shared__ __align__(16) __half wsT[64 * WSS];
    int tid = threadIdx.x;
    int w = tid >> 5, lane = tid & 31;
    int r0 = blockIdx.x * 128;
    int lq = lane >> 2;
    int lr = lane & 3;

    float acc[8][4];
#pragma unroll
    for (int t = 0; t < 8; t++)
#pragma unroll
        for (int q = 0; q < 4; q++) acc[t][q] = 0.f;

    for (int kc = 0; kc < F_IN; kc += 32) {
#pragma unroll
        for (int i = 0; i < 4; i++) {
            int idx = tid + 256 * i;
            int row = idx >> 3;
            int q   = idx & 7;
            float4 v = make_float4(0.f, 0.f, 0.f, 0.f);
            int gr = r0 + row;
            if (gr < n) v = *(const float4*)&x[(size_t)gr * F_IN + kc + q * 4];
            __half2 h01 = __floats2half2_rn(v.x, v.y);
            __half2 h23 = __floats2half2_rn(v.z, v.w);
            uint2 pv;
            pv.x = *(unsigned*)&h01; pv.y = *(unsigned*)&h23;
            *(uint2*)&xs[row * XSS + q * 4] = pv;
        }
#pragma unroll
        for (int i = 0; i < 2; i++) {
            int idx = tid + 256 * i;
            int k  = idx >> 4;
            int c4 = (idx & 15) * 4;
            float4 v = *(const float4*)&W[(size_t)(kc + k) * C1 + c4];
            wsT[(c4 + 0) * WSS + k] = __float2half_rn(v.x);
            wsT[(c4 + 1) * WSS + k] = __float2half_rn(v.y);
            wsT[(c4 + 2) * WSS + k] = __float2half_rn(v.z);
            wsT[(c4 + 3) * WSS + k] = __float2half_rn(v.w);
        }
        __syncthreads();
#pragma unroll
        for (int s = 0; s < 2; s++) {
            int r  = w * 16 + lq;
            int kb = s * 16 + lr * 2;
            unsigned a0 = *(const unsigned*)&xs[r * XSS + kb];
            unsigned a1 = *(const unsigned*)&xs[(r + 8) * XSS + kb];
            unsigned a2 = *(const unsigned*)&xs[r * XSS + kb + 8];
            unsigned a3 = *(const unsigned*)&xs[(r + 8) * XSS + kb + 8];
#pragma unroll
            for (int t = 0; t < 8; t++) {
                int nn = t * 8 + lq;
                unsigned b0 = *(const unsigned*)&wsT[nn * WSS + kb];
                unsigned b1 = *(const unsigned*)&wsT[nn * WSS + kb + 8];
                MMA16816(acc[t][0], acc[t][1], acc[t][2], acc[t][3],
                         a0, a1, a2, a3, b0, b1);
            }
        }
        __syncthreads();
    }

    int c0 = 2 * lr;
    int gra = r0 + w * 16 + lq;
    int grb = gra + 8;
    bool oka = gra < n, okb = grb < n;
#pragma unroll
    for (int t = 0; t < 8; t++) {
        float e0 = __ldg(&attS[8 * t + c0]);
        float e1 = __ldg(&attS[8 * t + c0 + 1]);
        float f0 = __ldg(&attD[8 * t + c0]);
        float f1 = __ldg(&attD[8 * t + c0 + 1]);
        float sa = fmaf(acc[t][0], e0, acc[t][1] * e1);
        float da = fmaf(acc[t][0], f0, acc[t][1] * f1);
        float sb = fmaf(acc[t][2], e0, acc[t][3] * e1);
        float db = fmaf(acc[t][2], f0, acc[t][3] * f1);
        sa += __shfl_xor_sync(0xffffffffu, sa, 1);
        sa += __shfl_xor_sync(0xffffffffu, sa, 2);
        da += __shfl_xor_sync(0xffffffffu, da, 1);
        da += __shfl_xor_sync(0xffffffffu, da, 2);
        sb += __shfl_xor_sync(0xffffffffu, sb, 1);
        sb += __shfl_xor_sync(0xffffffffu, sb, 2);
        db += __shfl_xor_sync(0xffffffffu, db, 1);
        db += __shfl_xor_sync(0xffffffffu, db, 2);
        if (oka) {
            *(float2*)&g_h1[(size_t)gra * C1 + 8 * t + c0] = make_float2(acc[t][0], acc[t][1]);
            if (lr == 0) { g_asrc1[gra * HEADS + t] = sa; g_adst1[gra * HEADS + t] = da; }
        }
        if (okb) {
            *(float2*)&g_h1[(size_t)grb * C1 + 8 * t + c0] = make_float2(acc[t][2], acc[t][3]);
            if (lr == 0) { g_asrc1[grb * HEADS + t] = sb; g_adst1[grb * HEADS + t] = db; }
        }
    }
}

// ================= single-pass block scan (last block folds scan2) =================
__device__ __forceinline__ int warp_incl_scan(int x) {
#pragma unroll
    for (int o = 1; o < 32; o <<= 1) {
        int t = __shfl_up_sync(0xffffffffu, x, o);
        if ((threadIdx.x & 31) >= o) x += t;
    }
    return x;
}

__global__ void k_scan1(int n, int nb) {
    __shared__ int wsum[8];
    __shared__ int is_last;
    int i = blockIdx.x * SCAN_B + threadIdx.x;
    int lane = threadIdx.x & 31, wid = threadIdx.x >> 5;
    if (i < n) g_tmp[i] = 0;
    int v = (i < n) ? g_deg[i] + 1 : 0;     // +1 = self-loop
    int x = warp_incl_scan(v);
    if (lane == 31) wsum[wid] = x;
    __syncthreads();
    if (wid == 0) {
        int y = (lane < 8) ? wsum[lane] : 0;
#pragma unroll
        for (int o = 1; o < 8; o <<= 1) {
            int t = __shfl_up_sync(0xffffffffu, y, o);
            if (lane >= o) y += t;
        }
        if (lane < 8) wsum[lane] = y;
    }
    __syncthreads();
    int excl = x - v + (wid > 0 ? wsum[wid - 1] : 0);
    if (i <= n) g_rowptr[i] = excl;
    if (threadIdx.x == 0) g_bsum[blockIdx.x] = wsum[7];

    __threadfence();
    if (threadIdx.x == 0) {
        int t = atomicAdd(&g_arrive, 1);
        is_last = (t == gridDim.x - 1);
    }
    __syncthreads();
    if (is_last) {
        int tt = threadIdx.x;
        int vv = (tt < nb) ? g_bsum[tt] : 0;
        int xx = warp_incl_scan(vv);
        if (lane == 31) wsum[wid] = xx;
        __syncthreads();
        if (wid == 0) {
            int y = (lane < 8) ? wsum[lane] : 0;
#pragma unroll
            for (int o = 1; o < 8; o <<= 1) {
                int t2 = __shfl_up_sync(0xffffffffu, y, o);
                if (lane >= o) y += t2;
            }
            if (lane < 8) wsum[lane] = y;
        }
        __syncthreads();
        int ex2 = xx - vv + (wid > 0 ? wsum[wid - 1] : 0);
        if (tt < nb) g_boff[tt] = ex2;
        if (tt == 0) g_arrive = 0;
    }
}

// ================= scatter (edges then self-loops) =================
__global__ void k_scatter(const void* __restrict__ ei, int E, int n) {
    long long e0 = (long long)blockIdx.x * 256;
    bool is64 = block_detect_is64((const int*)ei, e0, E);
    long long i = e0 + threadIdx.x;
    int s, d;
    if (i < E) {
        d = load_edge(ei, is64, (size_t)E + i);
        if ((unsigned)d >= (unsigned)n) return;
        s = load_edge(ei, is64, (size_t)i);
        if ((unsigned)s >= (unsigned)n) s = 0;
    } else if (i < E + n) {
        s = d = (int)(i - E);
    } else return;
    int pos = rowp(d) + atomicAdd(&g_tmp[d], 1);
    g_col[pos] = s;
}

// ================= layer-1 edge softmax + aggregate + bias + elu =================
// (R14 shape; launch_bounds(256,6) occupancy experiment: 48 -> <=40 regs)
__global__ __launch_bounds__(256, 6) void agg1(const float* __restrict__ bias1, int n) {
    int gwarp = (blockIdx.x * blockDim.x + threadIdx.x) >> 5;
    int lane  = threadIdx.x & 31;
    int half  = lane >> 4;
    int hl    = lane & 15;
    int half0 = half << 4;
    int nd = gwarp * 2 + half;
    bool okn = nd < n;
    int ndc = okn ? nd : 0;
    int h    = hl & 7;
    int j    = hl >> 3;
    int hown = hl >> 1;

    float adv = g_adst1[ndc * HEADS + h];
    int beg = rowp(ndc);
    int end = okn ? rowp(ndc + 1) : beg;

    ull acc01 = 0ull, acc23 = 0ull;
    float den = 0.f;

    int iters = (end - beg + 3) >> 2;
    int oth = __shfl_xor_sync(0xffffffffu, iters, 16);
    int mx = iters > oth ? iters : oth;

    for (int k = 0; k < mx; k++) {
        int e0 = beg + 4 * k;
        bool v0 = e0 < end, v1 = e0 + 1 < end, v2 = e0 + 2 < end, v3 = e0 + 3 < end;
        int s0 = g_col[v0 ? e0     : beg];
        int s1 = g_col[v1 ? e0 + 1 : beg];
        int s2 = g_col[v2 ? e0 + 2 : beg];
        int s3 = g_col[v3 ? e0 + 3 : beg];
        int sa = j ? s1 : s0;
        int sb = j ? s3 : s2;
        float aa = g_asrc1[sa * HEADS + h] + adv;
        float ab = g_asrc1[sb * HEADS + h] + adv;
        ulonglong2 u0 = *(const ulonglong2*)&g_h1[(size_t)s0 * C1 + 4 * hl];
        ulonglong2 u1 = *(const ulonglong2*)&g_h1[(size_t)s1 * C1 + 4 * hl];
        ulonglong2 u2 = *(const ulonglong2*)&g_h1[(size_t)s2 * C1 + 4 * hl];
        ulonglong2 u3 = *(const ulonglong2*)&g_h1[(size_t)s3 * C1 + 4 * hl];
        aa = aa > 0.f ? aa : 0.2f * aa;
        ab = ab > 0.f ? ab : 0.2f * ab;
        float wa = __expf(aa);
        float wb = __expf(ab);
        wa = (j ? v1 : v0) ? wa : 0.f;
        wb = (j ? v3 : v2) ? wb : 0.f;
        den += wa + wb;
        float w0o = __shfl_sync(0xffffffffu, wa, half0 + hown);
        float w1o = __shfl_sync(0xffffffffu, wa, half0 + 8 + hown);
        float w2o = __shfl_sync(0xffffffffu, wb, half0 + hown);
        float w3o = __shfl_sync(0xffffffffu, wb, half0 + 8 + hown);
        ull wp0, wp1, wp2, wp3;
        PACK_DUP_F32X2(wp0, w0o);
        PACK_DUP_F32X2(wp1, w1o);
        PACK_DUP_F32X2(wp2, w2o);
        PACK_DUP_F32X2(wp3, w3o);
        FMA_F32X2(acc01, wp0, u0.x, acc01);
        FMA_F32X2(acc23, wp0, u0.y, acc23);
        FMA_F32X2(acc01, wp1, u1.x, acc01);
        FMA_F32X2(acc23, wp1, u1.y, acc23);
        FMA_F32X2(acc01, wp2, u2.x, acc01);
        FMA_F32X2(acc23, wp2, u2.y, acc23);
        FMA_F32X2(acc01, wp3, u3.x, acc01);
        FMA_F32X2(acc23, wp3, u3.y, acc23);
    }

    den += __shfl_xor_sync(0xffffffffu, den, 8);
    float deno = __shfl_sync(0xffffffffu, den, half0 + hown);

    if (okn) {
        uint2 ua = *(uint2*)&acc01;
        uint2 ub = *(uint2*)&acc23;
        float4 bv = *(const float4*)&bias1[4 * hl];
        float o0 = __uint_as_float(ua.x) / deno + bv.x;
        float o1 = __uint_as_float(ua.y) / deno + bv.y;
        float o2 = __uint_as_float(ub.x) / deno + bv.z;
        float o3 = __uint_as_float(ub.y) / deno + bv.w;
        o0 = o0 > 0.f ? o0 : expm1f(o0);
        o1 = o1 > 0.f ? o1 : expm1f(o1);
        o2 = o2 > 0.f ? o2 : expm1f(o2);
        o3 = o3 > 0.f ? o3 : expm1f(o3);
        *(float4*)&g_h1act[(size_t)nd * C1 + 4 * hl] = make_float4(o0, o1, o2, o3);
    }
}

// ================= GEMM2: h2 = h1act @ W2, fused scalar logits =================
__global__ __launch_bounds__(256) void gemm2(
    const float* __restrict__ W2, const float* __restrict__ aS,
    const float* __restrict__ aD, int n)
{
    __shared__ float ws[64 * 16];
    int tid = threadIdx.x;
    for (int i = tid; i < 64 * 16; i += 256) ws[i] = W2[i];
    __syncthreads();

    int warp = tid >> 5, lane = tid & 31;
    int row0 = (blockIdx.x * 8 + warp) * 2 + (lane >> 4);
    int c = lane & 15;
    bool ok = row0 < n;
    int row = ok ? row0 : 0;

    float xr[4];
#pragma unroll
    for (int j = 0; j < 4; j++) xr[j] = g_h1act[(size_t)row * C1 + c + 16 * j];

    float acc = 0.f;
#pragma unroll
    for (int k = 0; k < 64; k++) {
        float xk = __shfl_sync(0xffffffffu, xr[k >> 4], (lane & 16) | (k & 15));
        acc = fmaf(xk, ws[k * 16 + c], acc);
    }

    float ts = acc * aS[c];
    float td = acc * aD[c];
#pragma unroll
    for (int off = 8; off >= 1; off >>= 1) {
        ts += __shfl_xor_sync(0xffffffffu, ts, off);
        td += __shfl_xor_sync(0xffffffffu, td, off);
    }
    if (ok) {
        g_h2[(size_t)row * CLS + c] = acc;
        if (c == 0) { g_asrc2[row] = ts; g_adst2[row] = td; }
    }
}

// ================= layer-2 aggregate + bias + log_softmax =================
// 4 nodes per warp (8 lanes each); lane p owns channels 2p, 2p+1 (float2/f32x2).
// w/den computed redundantly per lane -> NO shuffles, no fold in the loop.
__global__ __launch_bounds__(256) void agg2(
    const float* __restrict__ bias2, float* __restrict__ out, int n)
{
    int gwarp = (blockIdx.x * blockDim.x + threadIdx.x) >> 5;
    int lane = threadIdx.x & 31;
    int q = lane >> 3;            // quarter = node slot
    int p = lane & 7;             // channel pair owner
    int node = gwarp * 4 + q;
    bool ok = node < n;
    int nd = ok ? node : 0;

    float adv = g_adst2[nd];
    int beg = rowp(nd);
    int end = ok ? rowp(nd + 1) : beg;

    ull acc = 0ull;
    float den = 0.f;
    int e = beg;
    for (; e + 2 <= end; e += 2) {
        int s0 = g_col[e], s1 = g_col[e + 1];
        float a0 = g_asrc2[s0] + adv;
        float a1 = g_asrc2[s1] + adv;
        ull f0 = *(const ull*)&g_h2[(size_t)s0 * CLS + 2 * p];
        ull f1 = *(const ull*)&g_h2[(size_t)s1 * CLS + 2 * p];
        a0 = a0 > 0.f ? a0 : 0.2f * a0;
        a1 = a1 > 0.f ? a1 : 0.2f * a1;
        float w0 = __expf(a0), w1 = __expf(a1);
        den += w0 + w1;
        ull wp0, wp1;
        PACK_DUP_F32X2(wp0, w0);
        PACK_DUP_F32X2(wp1, w1);
        FMA_F32X2(acc, wp0, f0, acc);
        FMA_F32X2(acc, wp1, f1, acc);
    }
    if (e < end) {
        int s0 = g_col[e];
        float a0 = g_asrc2[s0] + adv;
        ull f0 = *(const ull*)&g_h2[(size_t)s0 * CLS + 2 * p];
        a0 = a0 > 0.f ? a0 : 0.2f * a0;
        float w0 = __expf(a0);
        den += w0;
        ull wp0;
        PACK_DUP_F32X2(wp0, w0);
        FMA_F32X2(acc, wp0, f0, acc);
    }

    uint2 u = *(uint2*)&acc;
    float2 bv = *(const float2*)&bias2[2 * p];
    float v0 = ok ? (__uint_as_float(u.x) / den + bv.x) : 0.f;
    float v1 = ok ? (__uint_as_float(u.y) / den + bv.y) : 0.f;

    // log_softmax over 16 channels = 8 lanes x 2 (xor 1,2,4 stays in the quarter)
    float m = fmaxf(v0, v1);
#pragma unroll
    for (int off = 4; off >= 1; off >>= 1)
        m = fmaxf(m, __shfl_xor_sync(0xffffffffu, m, off));
    float ex = __expf(v0 - m) + __expf(v1 - m);
#pragma unroll
    for (int off = 4; off >= 1; off >>= 1)
        ex += __shfl_xor_sync(0xffffffffu, ex, off);
    float ls = __logf(ex);
    if (ok)
        *(float2*)&out[(size_t)node * CLS + 2 * p] = make_float2(v0 - m - ls, v1 - m - ls);
}

// ---------------- launch ----------------
extern "C" void kernel_launch(void* const* d_in, const int* in_sizes, int n_in,
                              void* d_out, int out_size) {
    const float* x     = (const float*)d_in[0];
    const void*  ei    = d_in[1];
    const float* W1    = (const float*)d_in[2];
    const float* attS1 = (const float*)d_in[3];
    const float* attD1 = (const float*)d_in[4];
    const float* bias1 = (const float*)d_in[5];
    const float* W2    = (const float*)d_in[6];
    const float* attS2 = (const float*)d_in[7];
    const float* attD2 = (const float*)d_in[8];
    const float* bias2 = (const float*)d_in[9];
    float* out = (float*)d_out;

    int n = in_sizes[0] / F_IN;      // 50000
    int E = in_sizes[1] / 2;         // 1600000

    void* p_deg = nullptr;
    cudaGetSymbolAddress(&p_deg, g_deg);
    cudaMemsetAsync(p_deg, 0, (size_t)n * sizeof(int));

    int GB = (n + 127) / 128;                 // gemm1 blocks (391, 128-row tiles)
    int CB = (E + 255) / 256;                 // count blocks (6250)
    int nb = (n + SCAN_B - 1) / SCAN_B;       // scan blocks (196)
    int AW = (n + 1) / 2;                     // 2-node warps (agg1)
    int A4 = (n + 3) / 4;                     // 4-node warps (agg2)

    k_gemm1_count<<<GB + CB, 256>>>(x, W1, attS1, attD1, ei, n, E, GB);
    k_scan1<<<nb, SCAN_B>>>(n, nb);
    k_scatter<<<(E + n + 255) / 256, 256>>>(ei, E, n);
    agg1 <<<(AW + 7) / 8, 256>>>(bias1, n);     // <- ncu lands here
    gemm2<<<(n + 15) / 16, 256>>>(W2, attS2, attD2, n);
    agg2 <<<(A4 + 7) / 8, 256>>>(bias2, out, n);
}